// round 5
// baseline (speedup 1.0000x reference)
#include <cuda_runtime.h>
#include <cuda_bf16.h>
#include <cstdint>

// Problem constants
#define BB   32
#define CC   128
#define NN   64
#define HID  256

typedef unsigned long long ULL;

// ---------- packed f32x2 helpers ----------
__device__ __forceinline__ ULL pack2(float a, float b) {
    ULL r;
    asm("mov.b64 %0, {%1, %2};" : "=l"(r) : "r"(__float_as_uint(a)), "r"(__float_as_uint(b)));
    return r;
}
__device__ __forceinline__ void unpack2(ULL v, float& a, float& b) {
    unsigned lo, hi;
    asm("mov.b64 {%0, %1}, %2;" : "=r"(lo), "=r"(hi) : "l"(v));
    a = __uint_as_float(lo); b = __uint_as_float(hi);
}
__device__ __forceinline__ ULL fma2(ULL a, ULL b, ULL c) {
    ULL d;
    asm("fma.rn.f32x2 %0, %1, %2, %3;" : "=l"(d) : "l"(a), "l"(b), "l"(c));
    return d;
}

// ---------- device scratch (no allocations allowed) ----------
__device__ float g_rowscore[BB * NN];                 // row scores
__device__ float g_colpart[BB * NN * NN];             // per-(b,h) col partials
__device__ float g_colscore[BB * NN];                 // col scores
__device__ float g_P[2 * BB * NN * NN];               // [kind][b][i][j], kind0=row kind1=col

// =====================================================================
// Kernel 1: fused conv1+relu+conv2+relu+score partials.
// One block per (b,h): 64 pixels (w=0..63), 256 threads.
// thread: wg = tid&7 (owns w = wg*8..wg*8+7), og = tid>>3 (owns o = og*8..og*8+7)
// =====================================================================
#define WPAD 65
struct ConvSmem {
    float xs[CC * NN];          // 128x64 input slice        (32 KB)
    float h1[HID * NN];         // 256x64 hidden             (64 KB)
    float wbuf[HID * WPAD];     // weight chunk [256][65]    (65 KB)
    float wcol[HID];            // w_col[:,h]
    float colred[NN];
    float rowred;
};

__global__ void __launch_bounds__(256, 1) conv_score_kernel(
    const float* __restrict__ x,
    const float* __restrict__ w1, const float* __restrict__ b1,
    const float* __restrict__ w2, const float* __restrict__ b2,
    const float* __restrict__ w_row, const float* __restrict__ b_row,
    const float* __restrict__ w_col)
{
    extern __shared__ unsigned char dyn_smem[];
    ConvSmem* sm = reinterpret_cast<ConvSmem*>(dyn_smem);

    const int tid = threadIdx.x;
    const int bh  = blockIdx.x;
    const int b   = bh >> 6;
    const int h   = bh & 63;
    const int wg  = tid & 7;
    const int og  = tid >> 3;

    if (tid < NN) sm->colred[tid] = 0.f;
    if (tid == 0) sm->rowred = 0.f;
    sm->wcol[tid] = __ldg(&w_col[tid * NN + h]);

    // ---- load x[b, :, h, :] into xs[c][w] (coalesced float4) ----
    {
        const float4* xg = reinterpret_cast<const float4*>(x + (size_t)b * CC * NN * NN + (size_t)h * NN);
        #pragma unroll
        for (int j = 0; j < 8; j++) {
            int idx = tid + j * 256;          // 2048 float4 total
            int c   = idx >> 4;
            int w4  = idx & 15;
            float4 v = xg[(size_t)c * (NN * NN / 4) + w4];
            *reinterpret_cast<float4*>(&sm->xs[c * NN + w4 * 4]) = v;
        }
    }

    // ---- accumulators (8 o x 4 w-pairs), init with b1 ----
    ULL acc[8][4];
    #pragma unroll
    for (int i = 0; i < 8; i++) {
        float bv = __ldg(&b1[og * 8 + i]);
        ULL p = pack2(bv, bv);
        acc[i][0] = p; acc[i][1] = p; acc[i][2] = p; acc[i][3] = p;
    }

    // ---- conv1: 2 chunks of 64 input channels ----
    for (int cc = 0; cc < 2; cc++) {
        // stage w1[:, cc*64 .. +63] into wbuf (coalesced read, padded write)
        const float4* g4 = reinterpret_cast<const float4*>(w1);
        #pragma unroll
        for (int j = 0; j < 16; j++) {
            int idx = tid + j * 256;          // 4096 float4
            int r   = idx >> 4;
            int c4  = idx & 15;
            float4 v = g4[r * (CC / 4) + cc * 16 + c4];
            float* d = &sm->wbuf[r * WPAD + c4 * 4];
            d[0] = v.x; d[1] = v.y; d[2] = v.z; d[3] = v.w;
        }
        __syncthreads();

        #pragma unroll 2
        for (int c = 0; c < 64; c++) {
            const ULL* xrow = reinterpret_cast<const ULL*>(&sm->xs[(cc * 64 + c) * NN + wg * 8]);
            ULL xv0 = xrow[0], xv1 = xrow[1], xv2 = xrow[2], xv3 = xrow[3];
            #pragma unroll
            for (int i = 0; i < 8; i++) {
                float wv = sm->wbuf[(og * 8 + i) * WPAD + c];
                ULL wp2 = pack2(wv, wv);
                acc[i][0] = fma2(xv0, wp2, acc[i][0]);
                acc[i][1] = fma2(xv1, wp2, acc[i][1]);
                acc[i][2] = fma2(xv2, wp2, acc[i][2]);
                acc[i][3] = fma2(xv3, wp2, acc[i][3]);
            }
        }
        __syncthreads();
    }

    // ---- relu, store h1, re-init acc with b2 ----
    #pragma unroll
    for (int i = 0; i < 8; i++) {
        int o = og * 8 + i;
        #pragma unroll
        for (int wp = 0; wp < 4; wp++) {
            float a0, a1; unpack2(acc[i][wp], a0, a1);
            a0 = fmaxf(a0, 0.f); a1 = fmaxf(a1, 0.f);
            *reinterpret_cast<ULL*>(&sm->h1[o * NN + wg * 8 + wp * 2]) = pack2(a0, a1);
        }
        float bv = __ldg(&b2[o]);
        ULL p = pack2(bv, bv);
        acc[i][0] = p; acc[i][1] = p; acc[i][2] = p; acc[i][3] = p;
    }
    __syncthreads();

    // ---- conv2: 4 chunks of 64 channels ----
    for (int cc = 0; cc < 4; cc++) {
        const float4* g4 = reinterpret_cast<const float4*>(w2);
        #pragma unroll
        for (int j = 0; j < 16; j++) {
            int idx = tid + j * 256;
            int r   = idx >> 4;
            int c4  = idx & 15;
            float4 v = g4[r * (HID / 4) + cc * 16 + c4];
            float* d = &sm->wbuf[r * WPAD + c4 * 4];
            d[0] = v.x; d[1] = v.y; d[2] = v.z; d[3] = v.w;
        }
        __syncthreads();

        #pragma unroll 2
        for (int c = 0; c < 64; c++) {
            const ULL* xrow = reinterpret_cast<const ULL*>(&sm->h1[(cc * 64 + c) * NN + wg * 8]);
            ULL xv0 = xrow[0], xv1 = xrow[1], xv2 = xrow[2], xv3 = xrow[3];
            #pragma unroll
            for (int i = 0; i < 8; i++) {
                float wv = sm->wbuf[(og * 8 + i) * WPAD + c];
                ULL wp2 = pack2(wv, wv);
                acc[i][0] = fma2(xv0, wp2, acc[i][0]);
                acc[i][1] = fma2(xv1, wp2, acc[i][1]);
                acc[i][2] = fma2(xv2, wp2, acc[i][2]);
                acc[i][3] = fma2(xv3, wp2, acc[i][3]);
            }
        }
        __syncthreads();
    }

    // ---- relu h2 (registers) + score partials ----
    float rowp = 0.f;
    float colp[8];
    #pragma unroll
    for (int j = 0; j < 8; j++) colp[j] = 0.f;

    #pragma unroll
    for (int i = 0; i < 8; i++) {
        int o = og * 8 + i;
        float wc = sm->wcol[o];
        #pragma unroll
        for (int wp = 0; wp < 4; wp++) {
            float a0, a1; unpack2(acc[i][wp], a0, a1);
            a0 = fmaxf(a0, 0.f); a1 = fmaxf(a1, 0.f);
            float2 wr = __ldg(reinterpret_cast<const float2*>(&w_row[o * NN + wg * 8 + wp * 2]));
            rowp += a0 * wr.x + a1 * wr.y;
            colp[wp * 2]     += a0 * wc;
            colp[wp * 2 + 1] += a1 * wc;
        }
    }
    atomicAdd(&sm->rowred, rowp);
    #pragma unroll
    for (int j = 0; j < 8; j++) atomicAdd(&sm->colred[wg * 8 + j], colp[j]);
    __syncthreads();

    if (tid == 0)  g_rowscore[bh] = sm->rowred + __ldg(&b_row[0]);
    if (tid < NN)  g_colpart[bh * NN + tid] = sm->colred[tid];
}

// =====================================================================
// Kernel 2: reduce col partials over h
// =====================================================================
__global__ void col_reduce_kernel(const float* __restrict__ b_col)
{
    int b = blockIdx.x;
    int w = threadIdx.x;
    float s = __ldg(&b_col[0]);
    #pragma unroll 8
    for (int hh = 0; hh < NN; hh++) s += g_colpart[(b * NN + hh) * NN + w];
    g_colscore[b * NN + w] = s;
}

// =====================================================================
// Kernel 3: differentiable bitonic sort -> permutation matrix P
// 64 blocks: block s -> kind = s>>5 (0=row, 1=col), b = s&31
// =====================================================================
#define PPAD 65
__global__ void __launch_bounds__(256) sort_kernel()
{
    __shared__ float P[NN * PPAD];
    __shared__ float xsh[NN];
    __shared__ float alph[32];
    __shared__ int   pa[32], pb[32];

    const int tid  = threadIdx.x;
    const int s    = blockIdx.x;
    const int kind = s >> 5;
    const int b    = s & 31;
    const float* sc = kind ? g_colscore : g_rowscore;

    if (tid < NN) xsh[tid] = sc[b * NN + tid];
    for (int idx = tid; idx < NN * NN; idx += 256) {
        int r = idx >> 6, c = idx & 63;
        P[r * PPAD + c] = (r == c) ? 1.f : 0.f;
    }
    __syncthreads();

    for (int blk = 0; blk < 6; blk++) {
        for (int lay = 0; lay <= blk; lay++) {
            int m = 1 << (blk - lay);
            if (tid < 32) {
                int q  = tid;
                int ix = ((q & ~(m - 1)) << 1) | (q & (m - 1));
                int a = ix, bidx = ix + m;
                if ((ix >> (blk + 1)) & 1) { int t = a; a = bidx; bidx = t; }
                pa[q] = a; pb[q] = bidx;
                float xa = xsh[a], xb = xsh[bidx];
                float al = atanf((xb - xa) * 50.f) * 0.31830988618379067f + 0.5f;
                alph[q] = al;
                xsh[a]    = al * xa + (1.f - al) * xb;
                xsh[bidx] = (1.f - al) * xa + al * xb;
            }
            __syncthreads();
            #pragma unroll
            for (int it = 0; it < 8; it++) {
                int idx = tid + it * 256;             // 2048 = 64 rows x 32 pairs
                int r = idx >> 5, q = idx & 31;
                int a = pa[q], bidx = pb[q];
                float al = alph[q];
                float Pa = P[r * PPAD + a], Pb = P[r * PPAD + bidx];
                P[r * PPAD + a]    = al * Pa + (1.f - al) * Pb;
                P[r * PPAD + bidx] = (1.f - al) * Pa + al * Pb;
            }
            __syncthreads();
        }
    }

    for (int idx = tid; idx < NN * NN; idx += 256)
        g_P[(size_t)(kind * BB + b) * NN * NN + idx] = P[(idx >> 6) * PPAD + (idx & 63)];
}

// =====================================================================
// Kernel 4: out[b,c] = P_col * (P_row * X)^T     (one block per (b,c))
// =====================================================================
#define YPAD 68
struct ApplySmem {
    float Xs[NN * NN];      // 4096
    float Prs[NN * PPAD];   // 4160
    float Pcs[NN * PPAD];   // 4160
    float Yt[NN * YPAD];    // 4352 (stores (P_row X)^T)
};

__global__ void __launch_bounds__(256) apply_kernel(
    const float* __restrict__ x, float* __restrict__ out)
{
    extern __shared__ unsigned char dyn_smem[];
    ApplySmem* sm = reinterpret_cast<ApplySmem*>(dyn_smem);

    const int tid = threadIdx.x;
    const int bc  = blockIdx.x;
    const int b   = bc >> 7;

    // load X (this (b,c) 64x64 tile)
    {
        const float4* xg = reinterpret_cast<const float4*>(x) + (size_t)bc * (NN * NN / 4);
        float4* Xs4 = reinterpret_cast<float4*>(sm->Xs);
        #pragma unroll
        for (int j = 0; j < 4; j++) Xs4[tid + j * 256] = xg[tid + j * 256];
    }
    // load P_row, P_col into padded smem
    {
        const float4* pr4 = reinterpret_cast<const float4*>(&g_P[(size_t)b * NN * NN]);
        const float4* pc4 = reinterpret_cast<const float4*>(&g_P[(size_t)(BB + b) * NN * NN]);
        #pragma unroll
        for (int j = 0; j < 4; j++) {
            int idx = tid + j * 256;
            int l = idx * 4, r = l >> 6, c = l & 63;
            float4 v = pr4[idx];
            float* d = &sm->Prs[r * PPAD + c];
            d[0] = v.x; d[1] = v.y; d[2] = v.z; d[3] = v.w;
            float4 u = pc4[idx];
            float* e = &sm->Pcs[r * PPAD + c];
            e[0] = u.x; e[1] = u.y; e[2] = u.z; e[3] = u.w;
        }
    }
    __syncthreads();

    const int ig = tid >> 4, kg = tid & 15;
    const int i0 = ig * 4,   k0 = kg * 4;

    // phase 1: Y[i][k] = sum_j Prs[i][j] * X[j][k]
    ULL acc[4][2];
    #pragma unroll
    for (int ii = 0; ii < 4; ii++) { acc[ii][0] = 0ull; acc[ii][1] = 0ull; }

    #pragma unroll 4
    for (int j = 0; j < NN; j++) {
        const ULL* xp = reinterpret_cast<const ULL*>(&sm->Xs[j * NN + k0]);
        ULL xv0 = xp[0], xv1 = xp[1];
        #pragma unroll
        for (int ii = 0; ii < 4; ii++) {
            float p = sm->Prs[(i0 + ii) * PPAD + j];
            ULL pp = pack2(p, p);
            acc[ii][0] = fma2(xv0, pp, acc[ii][0]);
            acc[ii][1] = fma2(xv1, pp, acc[ii][1]);
        }
    }
    // write Y transposed: Yt[k][i] = Y[i][k]
    float yv[4][4];
    #pragma unroll
    for (int ii = 0; ii < 4; ii++) {
        unpack2(acc[ii][0], yv[ii][0], yv[ii][1]);
        unpack2(acc[ii][1], yv[ii][2], yv[ii][3]);
    }
    #pragma unroll
    for (int kk = 0; kk < 4; kk++) {
        float4 v = make_float4(yv[0][kk], yv[1][kk], yv[2][kk], yv[3][kk]);
        *reinterpret_cast<float4*>(&sm->Yt[(k0 + kk) * YPAD + i0]) = v;
    }
    __syncthreads();

    // phase 2: out[i][k] = sum_j Pcs[i][j] * Yt[j][k]
    #pragma unroll
    for (int ii = 0; ii < 4; ii++) { acc[ii][0] = 0ull; acc[ii][1] = 0ull; }

    #pragma unroll 4
    for (int j = 0; j < NN; j++) {
        const ULL* yp = reinterpret_cast<const ULL*>(&sm->Yt[j * YPAD + k0]);
        ULL yv0 = yp[0], yv1 = yp[1];
        #pragma unroll
        for (int ii = 0; ii < 4; ii++) {
            float p = sm->Pcs[(i0 + ii) * PPAD + j];
            ULL pp = pack2(p, p);
            acc[ii][0] = fma2(yv0, pp, acc[ii][0]);
            acc[ii][1] = fma2(yv1, pp, acc[ii][1]);
        }
    }

    float* og = out + (size_t)bc * NN * NN;
    #pragma unroll
    for (int ii = 0; ii < 4; ii++) {
        float o0, o1, o2, o3;
        unpack2(acc[ii][0], o0, o1);
        unpack2(acc[ii][1], o2, o3);
        *reinterpret_cast<float4*>(&og[(i0 + ii) * NN + k0]) = make_float4(o0, o1, o2, o3);
    }
}

// =====================================================================
// launcher
// =====================================================================
extern "C" void kernel_launch(void* const* d_in, const int* in_sizes, int n_in,
                              void* d_out, int out_size)
{
    const float* x     = (const float*)d_in[0];
    const float* w1    = (const float*)d_in[1];
    const float* b1    = (const float*)d_in[2];
    const float* w2    = (const float*)d_in[3];
    const float* b2    = (const float*)d_in[4];
    const float* w_row = (const float*)d_in[5];
    const float* b_row = (const float*)d_in[6];
    const float* w_col = (const float*)d_in[7];
    const float* b_col = (const float*)d_in[8];
    float* out = (float*)d_out;

    const int conv_smem  = (int)sizeof(ConvSmem);
    const int apply_smem = (int)sizeof(ApplySmem);
    cudaFuncSetAttribute(conv_score_kernel, cudaFuncAttributeMaxDynamicSharedMemorySize, conv_smem);
    cudaFuncSetAttribute(apply_kernel,      cudaFuncAttributeMaxDynamicSharedMemorySize, apply_smem);

    conv_score_kernel<<<BB * NN, 256, conv_smem>>>(x, w1, b1, w2, b2, w_row, b_row, w_col);
    col_reduce_kernel<<<BB, NN>>>(b_col);
    sort_kernel<<<2 * BB, 256>>>();
    apply_kernel<<<BB * CC, 256, apply_smem>>>(x, out);
}

// round 6
// speedup vs baseline: 1.0022x; 1.0022x over previous
#include <cuda_runtime.h>
#include <cuda_bf16.h>
#include <cstdint>

// Problem constants
#define BB   32
#define CC   128
#define NN   64
#define HID  256

typedef unsigned long long ULL;

// ---------- packed f32x2 helpers ----------
__device__ __forceinline__ ULL pack2(float a, float b) {
    ULL r;
    asm("mov.b64 %0, {%1, %2};" : "=l"(r) : "r"(__float_as_uint(a)), "r"(__float_as_uint(b)));
    return r;
}
__device__ __forceinline__ void unpack2(ULL v, float& a, float& b) {
    unsigned lo, hi;
    asm("mov.b64 {%0, %1}, %2;" : "=r"(lo), "=r"(hi) : "l"(v));
    a = __uint_as_float(lo); b = __uint_as_float(hi);
}
__device__ __forceinline__ ULL fma2(ULL a, ULL b, ULL c) {
    ULL d;
    asm("fma.rn.f32x2 %0, %1, %2, %3;" : "=l"(d) : "l"(a), "l"(b), "l"(c));
    return d;
}

// ---------- device scratch (no allocations allowed) ----------
__device__ float g_rowscore[BB * NN];                 // row scores
__device__ float g_colpart[BB * NN * NN];             // per-(b,h) col partials
__device__ float g_colscore[BB * NN];                 // col scores
__device__ float g_P[2 * BB * NN * NN];               // [kind][b][i][j], kind0=row kind1=col

// =====================================================================
// Kernel 1: fused conv1+relu+conv2+relu+score partials.
// One block per (b,h): 64 pixels (w=0..63), 256 threads.
// thread: wg = tid&7 (owns w = wg*8..wg*8+7), og = tid>>3 (owns o = og*8..og*8+7)
// =====================================================================
#define WPAD 65
struct ConvSmem {
    float xs[CC * NN];          // 128x64 input slice        (32 KB)
    float h1[HID * NN];         // 256x64 hidden             (64 KB)
    float wbuf[HID * WPAD];     // weight chunk [256][65]    (65 KB)
    float wcol[HID];            // w_col[:,h]
    float colred[NN];
    float rowred;
};

__global__ void __launch_bounds__(256, 1) conv_score_kernel(
    const float* __restrict__ x,
    const float* __restrict__ w1, const float* __restrict__ b1,
    const float* __restrict__ w2, const float* __restrict__ b2,
    const float* __restrict__ w_row, const float* __restrict__ b_row,
    const float* __restrict__ w_col)
{
    extern __shared__ unsigned char dyn_smem[];
    ConvSmem* sm = reinterpret_cast<ConvSmem*>(dyn_smem);

    const int tid = threadIdx.x;
    const int bh  = blockIdx.x;
    const int b   = bh >> 6;
    const int h   = bh & 63;
    const int wg  = tid & 7;
    const int og  = tid >> 3;

    if (tid < NN) sm->colred[tid] = 0.f;
    if (tid == 0) sm->rowred = 0.f;
    sm->wcol[tid] = __ldg(&w_col[tid * NN + h]);

    // ---- load x[b, :, h, :] into xs[c][w] (coalesced float4) ----
    {
        const float4* xg = reinterpret_cast<const float4*>(x + (size_t)b * CC * NN * NN + (size_t)h * NN);
        #pragma unroll
        for (int j = 0; j < 8; j++) {
            int idx = tid + j * 256;          // 2048 float4 total
            int c   = idx >> 4;
            int w4  = idx & 15;
            float4 v = xg[(size_t)c * (NN * NN / 4) + w4];
            *reinterpret_cast<float4*>(&sm->xs[c * NN + w4 * 4]) = v;
        }
    }

    // ---- accumulators (8 o x 4 w-pairs), init with b1 ----
    ULL acc[8][4];
    #pragma unroll
    for (int i = 0; i < 8; i++) {
        float bv = __ldg(&b1[og * 8 + i]);
        ULL p = pack2(bv, bv);
        acc[i][0] = p; acc[i][1] = p; acc[i][2] = p; acc[i][3] = p;
    }

    // ---- conv1: 2 chunks of 64 input channels ----
    for (int cc = 0; cc < 2; cc++) {
        // stage w1[:, cc*64 .. +63] into wbuf (coalesced read, padded write)
        const float4* g4 = reinterpret_cast<const float4*>(w1);
        #pragma unroll
        for (int j = 0; j < 16; j++) {
            int idx = tid + j * 256;          // 4096 float4
            int r   = idx >> 4;
            int c4  = idx & 15;
            float4 v = g4[r * (CC / 4) + cc * 16 + c4];
            float* d = &sm->wbuf[r * WPAD + c4 * 4];
            d[0] = v.x; d[1] = v.y; d[2] = v.z; d[3] = v.w;
        }
        __syncthreads();

        #pragma unroll 2
        for (int c = 0; c < 64; c++) {
            const ULL* xrow = reinterpret_cast<const ULL*>(&sm->xs[(cc * 64 + c) * NN + wg * 8]);
            ULL xv0 = xrow[0], xv1 = xrow[1], xv2 = xrow[2], xv3 = xrow[3];
            #pragma unroll
            for (int i = 0; i < 8; i++) {
                float wv = sm->wbuf[(og * 8 + i) * WPAD + c];
                ULL wp2 = pack2(wv, wv);
                acc[i][0] = fma2(xv0, wp2, acc[i][0]);
                acc[i][1] = fma2(xv1, wp2, acc[i][1]);
                acc[i][2] = fma2(xv2, wp2, acc[i][2]);
                acc[i][3] = fma2(xv3, wp2, acc[i][3]);
            }
        }
        __syncthreads();
    }

    // ---- relu, store h1, re-init acc with b2 ----
    #pragma unroll
    for (int i = 0; i < 8; i++) {
        int o = og * 8 + i;
        #pragma unroll
        for (int wp = 0; wp < 4; wp++) {
            float a0, a1; unpack2(acc[i][wp], a0, a1);
            a0 = fmaxf(a0, 0.f); a1 = fmaxf(a1, 0.f);
            *reinterpret_cast<ULL*>(&sm->h1[o * NN + wg * 8 + wp * 2]) = pack2(a0, a1);
        }
        float bv = __ldg(&b2[o]);
        ULL p = pack2(bv, bv);
        acc[i][0] = p; acc[i][1] = p; acc[i][2] = p; acc[i][3] = p;
    }
    __syncthreads();

    // ---- conv2: 4 chunks of 64 channels ----
    for (int cc = 0; cc < 4; cc++) {
        const float4* g4 = reinterpret_cast<const float4*>(w2);
        #pragma unroll
        for (int j = 0; j < 16; j++) {
            int idx = tid + j * 256;
            int r   = idx >> 4;
            int c4  = idx & 15;
            float4 v = g4[r * (HID / 4) + cc * 16 + c4];
            float* d = &sm->wbuf[r * WPAD + c4 * 4];
            d[0] = v.x; d[1] = v.y; d[2] = v.z; d[3] = v.w;
        }
        __syncthreads();

        #pragma unroll 2
        for (int c = 0; c < 64; c++) {
            const ULL* xrow = reinterpret_cast<const ULL*>(&sm->h1[(cc * 64 + c) * NN + wg * 8]);
            ULL xv0 = xrow[0], xv1 = xrow[1], xv2 = xrow[2], xv3 = xrow[3];
            #pragma unroll
            for (int i = 0; i < 8; i++) {
                float wv = sm->wbuf[(og * 8 + i) * WPAD + c];
                ULL wp2 = pack2(wv, wv);
                acc[i][0] = fma2(xv0, wp2, acc[i][0]);
                acc[i][1] = fma2(xv1, wp2, acc[i][1]);
                acc[i][2] = fma2(xv2, wp2, acc[i][2]);
                acc[i][3] = fma2(xv3, wp2, acc[i][3]);
            }
        }
        __syncthreads();
    }

    // ---- relu h2 (registers) + score partials ----
    float rowp = 0.f;
    float colp[8];
    #pragma unroll
    for (int j = 0; j < 8; j++) colp[j] = 0.f;

    #pragma unroll
    for (int i = 0; i < 8; i++) {
        int o = og * 8 + i;
        float wc = sm->wcol[o];
        #pragma unroll
        for (int wp = 0; wp < 4; wp++) {
            float a0, a1; unpack2(acc[i][wp], a0, a1);
            a0 = fmaxf(a0, 0.f); a1 = fmaxf(a1, 0.f);
            float2 wr = __ldg(reinterpret_cast<const float2*>(&w_row[o * NN + wg * 8 + wp * 2]));
            rowp += a0 * wr.x + a1 * wr.y;
            colp[wp * 2]     += a0 * wc;
            colp[wp * 2 + 1] += a1 * wc;
        }
    }
    atomicAdd(&sm->rowred, rowp);
    #pragma unroll
    for (int j = 0; j < 8; j++) atomicAdd(&sm->colred[wg * 8 + j], colp[j]);
    __syncthreads();

    if (tid == 0)  g_rowscore[bh] = sm->rowred + __ldg(&b_row[0]);
    if (tid < NN)  g_colpart[bh * NN + tid] = sm->colred[tid];
}

// =====================================================================
// Kernel 2: reduce col partials over h
// =====================================================================
__global__ void col_reduce_kernel(const float* __restrict__ b_col)
{
    int b = blockIdx.x;
    int w = threadIdx.x;
    float s = __ldg(&b_col[0]);
    #pragma unroll 8
    for (int hh = 0; hh < NN; hh++) s += g_colpart[(b * NN + hh) * NN + w];
    g_colscore[b * NN + w] = s;
}

// =====================================================================
// Kernel 3: differentiable bitonic sort -> permutation matrix P
// 64 blocks: block s -> kind = s>>5 (0=row, 1=col), b = s&31
// =====================================================================
#define PPAD 65
__global__ void __launch_bounds__(256) sort_kernel()
{
    __shared__ float P[NN * PPAD];
    __shared__ float xsh[NN];
    __shared__ float alph[32];
    __shared__ int   pa[32], pb[32];

    const int tid  = threadIdx.x;
    const int s    = blockIdx.x;
    const int kind = s >> 5;
    const int b    = s & 31;
    const float* sc = kind ? g_colscore : g_rowscore;

    if (tid < NN) xsh[tid] = sc[b * NN + tid];
    for (int idx = tid; idx < NN * NN; idx += 256) {
        int r = idx >> 6, c = idx & 63;
        P[r * PPAD + c] = (r == c) ? 1.f : 0.f;
    }
    __syncthreads();

    for (int blk = 0; blk < 6; blk++) {
        for (int lay = 0; lay <= blk; lay++) {
            int m = 1 << (blk - lay);
            if (tid < 32) {
                int q  = tid;
                int ix = ((q & ~(m - 1)) << 1) | (q & (m - 1));
                int a = ix, bidx = ix + m;
                if ((ix >> (blk + 1)) & 1) { int t = a; a = bidx; bidx = t; }
                pa[q] = a; pb[q] = bidx;
                float xa = xsh[a], xb = xsh[bidx];
                float al = atanf((xb - xa) * 50.f) * 0.31830988618379067f + 0.5f;
                alph[q] = al;
                xsh[a]    = al * xa + (1.f - al) * xb;
                xsh[bidx] = (1.f - al) * xa + al * xb;
            }
            __syncthreads();
            #pragma unroll
            for (int it = 0; it < 8; it++) {
                int idx = tid + it * 256;             // 2048 = 64 rows x 32 pairs
                int r = idx >> 5, q = idx & 31;
                int a = pa[q], bidx = pb[q];
                float al = alph[q];
                float Pa = P[r * PPAD + a], Pb = P[r * PPAD + bidx];
                P[r * PPAD + a]    = al * Pa + (1.f - al) * Pb;
                P[r * PPAD + bidx] = (1.f - al) * Pa + al * Pb;
            }
            __syncthreads();
        }
    }

    for (int idx = tid; idx < NN * NN; idx += 256)
        g_P[(size_t)(kind * BB + b) * NN * NN + idx] = P[(idx >> 6) * PPAD + (idx & 63)];
}

// =====================================================================
// Kernel 4: out[b,c] = P_col * (P_row * X)^T     (one block per (b,c))
// =====================================================================
#define YPAD 68
struct ApplySmem {
    float Xs[NN * NN];      // 4096
    float Prs[NN * PPAD];   // 4160
    float Pcs[NN * PPAD];   // 4160
    float Yt[NN * YPAD];    // 4352 (stores (P_row X)^T)
};

__global__ void __launch_bounds__(256) apply_kernel(
    const float* __restrict__ x, float* __restrict__ out)
{
    extern __shared__ unsigned char dyn_smem[];
    ApplySmem* sm = reinterpret_cast<ApplySmem*>(dyn_smem);

    const int tid = threadIdx.x;
    const int bc  = blockIdx.x;
    const int b   = bc >> 7;

    // load X (this (b,c) 64x64 tile)
    {
        const float4* xg = reinterpret_cast<const float4*>(x) + (size_t)bc * (NN * NN / 4);
        float4* Xs4 = reinterpret_cast<float4*>(sm->Xs);
        #pragma unroll
        for (int j = 0; j < 4; j++) Xs4[tid + j * 256] = xg[tid + j * 256];
    }
    // load P_row, P_col into padded smem
    {
        const float4* pr4 = reinterpret_cast<const float4*>(&g_P[(size_t)b * NN * NN]);
        const float4* pc4 = reinterpret_cast<const float4*>(&g_P[(size_t)(BB + b) * NN * NN]);
        #pragma unroll
        for (int j = 0; j < 4; j++) {
            int idx = tid + j * 256;
            int l = idx * 4, r = l >> 6, c = l & 63;
            float4 v = pr4[idx];
            float* d = &sm->Prs[r * PPAD + c];
            d[0] = v.x; d[1] = v.y; d[2] = v.z; d[3] = v.w;
            float4 u = pc4[idx];
            float* e = &sm->Pcs[r * PPAD + c];
            e[0] = u.x; e[1] = u.y; e[2] = u.z; e[3] = u.w;
        }
    }
    __syncthreads();

    const int ig = tid >> 4, kg = tid & 15;
    const int i0 = ig * 4,   k0 = kg * 4;

    // phase 1: Y[i][k] = sum_j Prs[i][j] * X[j][k]
    ULL acc[4][2];
    #pragma unroll
    for (int ii = 0; ii < 4; ii++) { acc[ii][0] = 0ull; acc[ii][1] = 0ull; }

    #pragma unroll 4
    for (int j = 0; j < NN; j++) {
        const ULL* xp = reinterpret_cast<const ULL*>(&sm->Xs[j * NN + k0]);
        ULL xv0 = xp[0], xv1 = xp[1];
        #pragma unroll
        for (int ii = 0; ii < 4; ii++) {
            float p = sm->Prs[(i0 + ii) * PPAD + j];
            ULL pp = pack2(p, p);
            acc[ii][0] = fma2(xv0, pp, acc[ii][0]);
            acc[ii][1] = fma2(xv1, pp, acc[ii][1]);
        }
    }
    // write Y transposed: Yt[k][i] = Y[i][k]
    float yv[4][4];
    #pragma unroll
    for (int ii = 0; ii < 4; ii++) {
        unpack2(acc[ii][0], yv[ii][0], yv[ii][1]);
        unpack2(acc[ii][1], yv[ii][2], yv[ii][3]);
    }
    #pragma unroll
    for (int kk = 0; kk < 4; kk++) {
        float4 v = make_float4(yv[0][kk], yv[1][kk], yv[2][kk], yv[3][kk]);
        *reinterpret_cast<float4*>(&sm->Yt[(k0 + kk) * YPAD + i0]) = v;
    }
    __syncthreads();

    // phase 2: out[i][k] = sum_j Pcs[i][j] * Yt[j][k]
    #pragma unroll
    for (int ii = 0; ii < 4; ii++) { acc[ii][0] = 0ull; acc[ii][1] = 0ull; }

    #pragma unroll 4
    for (int j = 0; j < NN; j++) {
        const ULL* yp = reinterpret_cast<const ULL*>(&sm->Yt[j * YPAD + k0]);
        ULL yv0 = yp[0], yv1 = yp[1];
        #pragma unroll
        for (int ii = 0; ii < 4; ii++) {
            float p = sm->Pcs[(i0 + ii) * PPAD + j];
            ULL pp = pack2(p, p);
            acc[ii][0] = fma2(yv0, pp, acc[ii][0]);
            acc[ii][1] = fma2(yv1, pp, acc[ii][1]);
        }
    }

    float* og = out + (size_t)bc * NN * NN;
    #pragma unroll
    for (int ii = 0; ii < 4; ii++) {
        float o0, o1, o2, o3;
        unpack2(acc[ii][0], o0, o1);
        unpack2(acc[ii][1], o2, o3);
        *reinterpret_cast<float4*>(&og[(i0 + ii) * NN + k0]) = make_float4(o0, o1, o2, o3);
    }
}

// =====================================================================
// launcher
// =====================================================================
extern "C" void kernel_launch(void* const* d_in, const int* in_sizes, int n_in,
                              void* d_out, int out_size)
{
    const float* x     = (const float*)d_in[0];
    const float* w1    = (const float*)d_in[1];
    const float* b1    = (const float*)d_in[2];
    const float* w2    = (const float*)d_in[3];
    const float* b2    = (const float*)d_in[4];
    const float* w_row = (const float*)d_in[5];
    const float* b_row = (const float*)d_in[6];
    const float* w_col = (const float*)d_in[7];
    const float* b_col = (const float*)d_in[8];
    float* out = (float*)d_out;

    const int conv_smem  = (int)sizeof(ConvSmem);
    const int apply_smem = (int)sizeof(ApplySmem);
    cudaFuncSetAttribute(conv_score_kernel, cudaFuncAttributeMaxDynamicSharedMemorySize, conv_smem);
    cudaFuncSetAttribute(apply_kernel,      cudaFuncAttributeMaxDynamicSharedMemorySize, apply_smem);

    conv_score_kernel<<<BB * NN, 256, conv_smem>>>(x, w1, b1, w2, b2, w_row, b_row, w_col);
    col_reduce_kernel<<<BB, NN>>>(b_col);
    sort_kernel<<<2 * BB, 256>>>();
    apply_kernel<<<BB * CC, 256, apply_smem>>>(x, out);
}